// round 2
// baseline (speedup 1.0000x reference)
#include <cuda_runtime.h>
#include <cstdint>

// ---------------------------------------------------------------------------
// Tree_Stoch_GLM: gumbel-softmax routing + skinny GEMM + causal FIR +
// triangular "recurrence" (a 20-level feed-forward DAG in time, NOT a scan).
#define SUBN 20
#define TLEN 50000
#define TNO  200
#define ENO  2000
#define INO  500
#define RT   50048        // padded row stride for [20][T] buffers
#define EPSG 1e-7f

// ------------------------- scratch (device globals) ------------------------
__device__ float g_Ce[SUBN * ENO];
__device__ float g_Ci[SUBN * INO];
__device__ float g_Wd[SUBN * SUBN];     // C_den[i][j] * exp(W_sub[j])
__device__ float g_synTe[SUBN * RT];    // syn_e transposed [s][t]
__device__ float g_synTi[SUBN * RT];
__device__ float g_A[SUBN * RT];        // filtered_e+filtered_i+Theta, [s][t]

// ---------------------------------------------------------------------------
// C_syn (e or i): per-column gumbel-softmax over 20 subunits (argmax if test).
__global__ void k_csyn(const float* __restrict__ logit, const float* __restrict__ u,
                       const float* __restrict__ temp, const int* __restrict__ test,
                       float* __restrict__ Cout, int E, int which)
{
    int j = blockIdx.x * blockDim.x + threadIdx.x;
    if (j >= E) return;
    float* Cs = which ? g_Ci : g_Ce;

    float v[SUBN];
    if (*test) {
        int am = 0; float b = logit[j];
        #pragma unroll
        for (int s = 1; s < SUBN; s++) {
            float l = logit[s * E + j];
            if (l > b) { b = l; am = s; }
        }
        #pragma unroll
        for (int s = 0; s < SUBN; s++) v[s] = (s == am) ? 1.f : 0.f;
    } else {
        float tp = *temp;
        float mx = -3.0e38f;
        #pragma unroll
        for (int s = 0; s < SUBN; s++) {
            float uu = u[s * E + j];
            float g = -logf(-logf(uu + EPSG) + EPSG);
            float y = (logit[s * E + j] + g) / tp;
            v[s] = y;
            mx = fmaxf(mx, y);
        }
        float sum = 0.f;
        #pragma unroll
        for (int s = 0; s < SUBN; s++) { v[s] = expf(v[s] - mx); sum += v[s]; }
        float inv = 1.f / sum;
        #pragma unroll
        for (int s = 0; s < SUBN; s++) v[s] *= inv;
    }
    #pragma unroll
    for (int s = 0; s < SUBN; s++) {
        Cs[s * E + j] = v[s];
        if (Cout) Cout[s * E + j] = v[s];
    }
}

// ---------------------------------------------------------------------------
// C_den: column j>=2, candidate parent rows 0..j-1 at linear offset
// j*(j-1)/2 - 1. Column 1: row 0 = 1. Gumbel noise divided by temp (raw
// logits NOT), matching the reference. Also g_Wd[i][j] = C_den[i][j]*exp(W_sub[j]).
__global__ void k_cden(const float* __restrict__ raw, const float* __restrict__ u_den,
                       const float* __restrict__ W_sub, const float* __restrict__ temp,
                       const int* __restrict__ test, float* __restrict__ Cout)
{
    int j = threadIdx.x;
    if (j >= SUBN) return;

    float col[SUBN];
    #pragma unroll
    for (int r = 0; r < SUBN; r++) col[r] = 0.f;

    if (j == 1) col[0] = 1.f;
    if (j >= 2) {
        int off = j * (j - 1) / 2 - 1;
        if (*test) {
            int am = 0; float b = raw[off];
            for (int r = 1; r < j; r++)
                if (raw[off + r] > b) { b = raw[off + r]; am = r; }
            col[am] = 1.f;
        } else {
            float tp = *temp;
            float v[SUBN];
            float mx = -3.0e38f;
            for (int r = 0; r < j; r++) {
                float uu = u_den[off + r];
                float g = -logf(-logf(uu + EPSG) + EPSG);
                v[r] = raw[off + r] + g / tp;
                mx = fmaxf(mx, v[r]);
            }
            float sum = 0.f;
            for (int r = 0; r < j; r++) { v[r] = expf(v[r] - mx); sum += v[r]; }
            float inv = 1.f / sum;
            for (int r = 0; r < j; r++) col[r] = v[r] * inv;
        }
    }
    float gj = expf(W_sub[j]);
    #pragma unroll
    for (int r = 0; r < SUBN; r++) {
        if (Cout) Cout[r * SUBN + j] = col[r];
        g_Wd[r * SUBN + j] = col[r] * gj;
    }
}

// ---------------------------------------------------------------------------
// out_filters = vstack(W_syn[:,:,0], W_syn[:,:,1])  (W_syn is [20][200][2])
__global__ void k_filtout(const float* __restrict__ W_syn, float* __restrict__ outF)
{
    int idx = blockIdx.x * blockDim.x + threadIdx.x;
    if (idx >= 2 * SUBN * TNO) return;
    int r = idx / TNO, c = idx % TNO;
    int ch = r / SUBN, s = r % SUBN;
    outF[idx] = W_syn[s * (TNO * 2) + c * 2 + ch];
}

// ---------------------------------------------------------------------------
// Skinny GEMM: synT[s][t] = sum_k S[t][k] * C[s][k]  (N=20).
// gridDim.y selects stream (0: e with K=2000, 1: i with K=500).
// 128 threads = 4 warps; warp w owns subunits 5w..5w+4 (uniform C loads);
// lane L owns t-pairs {2L, 64+2L} -> contiguous conflict-free LDS.64.
// fma.rn.f32x2 doubles fp32 MAC throughput.
#define G_BT 128
#define G_KC 20
#define G_TH 128

__global__ void __launch_bounds__(G_TH) k_gemm(const float* __restrict__ Se,
                                               const float* __restrict__ Si)
{
    __shared__ __align__(16) float sS[G_KC][G_BT + 2];   // [k][t], even pitch
    __shared__ float sC[SUBN][G_KC];

    const int which = blockIdx.y;
    const float* __restrict__ S  = which ? Si : Se;
    const float* __restrict__ Cs = which ? g_Ci : g_Ce;
    float* __restrict__ synT     = which ? g_synTi : g_synTe;
    const int K = which ? INO : ENO;

    const int t0   = blockIdx.x * G_BT;
    const int w    = threadIdx.x >> 5;   // warp = subunit group
    const int lane = threadIdx.x & 31;

    unsigned long long acc[2][5];
    #pragma unroll
    for (int p = 0; p < 2; p++)
        #pragma unroll
        for (int s = 0; s < 5; s++) acc[p][s] = 0ull;

    for (int k0 = 0; k0 < K; k0 += G_KC) {
        // stage S tile [128 t][20 k] transposed into smem (float4 loads)
        #pragma unroll
        for (int it = 0; it < 5; it++) {
            int lin = threadIdx.x + it * G_TH;     // 0..639 (640 float4)
            int row = lin / 5;                      // t within tile
            int c4  = lin % 5;                      // which float4 of 20 k
            int t = t0 + row; if (t > TLEN - 1) t = TLEN - 1;
            float4 vv = *reinterpret_cast<const float4*>(&S[(size_t)t * K + k0 + c4 * 4]);
            sS[c4 * 4 + 0][row] = vv.x;
            sS[c4 * 4 + 1][row] = vv.y;
            sS[c4 * 4 + 2][row] = vv.z;
            sS[c4 * 4 + 3][row] = vv.w;
        }
        for (int lin = threadIdx.x; lin < SUBN * G_KC; lin += G_TH) {
            int s = lin / G_KC, kk = lin % G_KC;
            sC[s][kk] = Cs[s * K + k0 + kk];
        }
        __syncthreads();

        #pragma unroll
        for (int kk = 0; kk < G_KC; kk++) {
            unsigned long long a0 =
                *reinterpret_cast<const unsigned long long*>(&sS[kk][2 * lane]);
            unsigned long long a1 =
                *reinterpret_cast<const unsigned long long*>(&sS[kk][64 + 2 * lane]);
            #pragma unroll
            for (int s = 0; s < 5; s++) {
                float c = sC[w * 5 + s][kk];        // uniform within warp
                unsigned long long c2;
                asm("mov.b64 %0, {%1, %1};" : "=l"(c2) : "r"(__float_as_uint(c)));
                asm("fma.rn.f32x2 %0, %1, %2, %3;"
                    : "=l"(acc[0][s]) : "l"(a0), "l"(c2), "l"(acc[0][s]));
                asm("fma.rn.f32x2 %0, %1, %2, %3;"
                    : "=l"(acc[1][s]) : "l"(a1), "l"(c2), "l"(acc[1][s]));
            }
        }
        __syncthreads();
    }

    #pragma unroll
    for (int s = 0; s < 5; s++)
        #pragma unroll
        for (int p = 0; p < 2; p++) {
            int t = t0 + 64 * p + 2 * lane;         // t even, TLEN even
            if (t < TLEN)
                *reinterpret_cast<unsigned long long*>(&synT[(w * 5 + s) * RT + t]) = acc[p][s];
        }
}

// ---------------------------------------------------------------------------
// Causal FIR (200 taps), e+i streams packed as f32x2, fused + Theta:
//   A[s][t] = Theta[s] + sum_tau (synTe[t-tau]*We[tau] + synTi[t-tau]*Wi[tau])
// Rolling packed register window; refills batched 8 taps via 2 x LDS.128.
#define F_BT 2048
#define F_TH 256
#define F_PAD 9                                // front pad -> base even (16B align)
#define F_W  (F_BT + TNO - 1 + F_PAD)          // 2256 float2 slots

__global__ void __launch_bounds__(F_TH) k_filter(const float* __restrict__ W_syn,
                                                 const float* __restrict__ Theta)
{
    __shared__ __align__(16) float2 sei[F_W];
    __shared__ float2 wei[TNO];
    const int s  = blockIdx.y;
    const int t0 = blockIdx.x * F_BT;

    for (int l = threadIdx.x; l < F_W; l += F_TH) {
        int t = t0 - (TNO - 1) + (l - F_PAD);
        float2 v = make_float2(0.f, 0.f);
        if (l >= F_PAD && t >= 0 && t < TLEN) {
            v.x = g_synTe[s * RT + t];
            v.y = g_synTi[s * RT + t];
        }
        sei[l] = v;
    }
    if (threadIdx.x < TNO)   // W_syn[s][tau][{0,1}] is already {e,i} interleaved
        wei[threadIdx.x] = reinterpret_cast<const float2*>(W_syn + s * TNO * 2)[threadIdx.x];
    __syncthreads();

    const int base = F_PAD + (TNO - 1) + threadIdx.x * 8;   // even -> 16B aligned refs
    unsigned long long acc2[8], ev[8];
    #pragma unroll
    for (int i = 0; i < 8; i++) {
        acc2[i] = 0ull;
        ev[i] = *reinterpret_cast<const unsigned long long*>(&sei[base + i]);
    }

    for (int tau0 = 0; tau0 < TNO; tau0 += 8) {
        // refill buffer: rv[k] = sei[base - tau0 - 8 + k]; used as ev[0]=rv[7-j]
        float4 rva = *reinterpret_cast<const float4*>(&sei[base - tau0 - 8]);
        float4 rvb = *reinterpret_cast<const float4*>(&sei[base - tau0 - 4]);
        unsigned long long rv[4];
        rv[0] = *reinterpret_cast<unsigned long long*>(&rva.x);
        rv[1] = *reinterpret_cast<unsigned long long*>(&rva.z);
        rv[2] = *reinterpret_cast<unsigned long long*>(&rvb.x);
        rv[3] = *reinterpret_cast<unsigned long long*>(&rvb.z);
        #pragma unroll
        for (int j = 0; j < 8; j++) {
            unsigned long long wv =
                *reinterpret_cast<const unsigned long long*>(&wei[tau0 + j]);
            #pragma unroll
            for (int i = 0; i < 8; i++)
                asm("fma.rn.f32x2 %0, %1, %2, %3;"
                    : "=l"(acc2[i]) : "l"(ev[i]), "l"(wv), "l"(acc2[i]));
            #pragma unroll
            for (int i = 7; i > 0; i--) ev[i] = ev[i - 1];
            int k = 7 - j;                       // rv[k] holds sei[base - (tau0+j) - 1]
            ev[0] = rv[k >> 1];
            if (k & 1) ev[0] >>= 0;              // placeholder; resolved below
            // select proper half: rv holds float2 pairs; k even -> pair (k, k+1)
            // We stored rv as 4 u64 each = one float2 = one (e,i) slot. k indexes slots.
            ev[0] = rv[k] ;
        }
    }
    // NOTE: rv must hold 8 slots; fix: widen to 8 u64 (see rv2 below).
    float th = Theta[s];
    #pragma unroll
    for (int i = 0; i < 8; i++) {
        float lo = __uint_as_float((unsigned)(acc2[i] & 0xffffffffull));
        float hi = __uint_as_float((unsigned)(acc2[i] >> 32));
        int t = t0 + threadIdx.x * 8 + i;
        if (t < TLEN) g_A[s * RT + t] = lo + hi + th;
    }
}

// The version above had a slot-indexing bug (rv[4] vs 8 slots). Provide the
// corrected filter actually used:
__global__ void __launch_bounds__(F_TH) k_filter2(const float* __restrict__ W_syn,
                                                  const float* __restrict__ Theta)
{
    __shared__ __align__(16) float2 sei[F_W];
    __shared__ float2 wei[TNO];
    const int s  = blockIdx.y;
    const int t0 = blockIdx.x * F_BT;

    for (int l = threadIdx.x; l < F_W; l += F_TH) {
        int t = t0 - (TNO - 1) + (l - F_PAD);
        float2 v = make_float2(0.f, 0.f);
        if (l >= F_PAD && t >= 0 && t < TLEN) {
            v.x = g_synTe[s * RT + t];
            v.y = g_synTi[s * RT + t];
        }
        sei[l] = v;
    }
    if (threadIdx.x < TNO)
        wei[threadIdx.x] = reinterpret_cast<const float2*>(W_syn + s * TNO * 2)[threadIdx.x];
    __syncthreads();

    const int base = F_PAD + (TNO - 1) + threadIdx.x * 8;
    unsigned long long acc2[8], ev[8];
    #pragma unroll
    for (int i = 0; i < 8; i++) {
        acc2[i] = 0ull;
        ev[i] = *reinterpret_cast<const unsigned long long*>(&sei[base + i]);
    }

    for (int tau0 = 0; tau0 < TNO; tau0 += 8) {
        unsigned long long rv[8];   // rv[k] = sei[base - tau0 - 8 + k]
        {
            uint4 p0 = *reinterpret_cast<const uint4*>(&sei[base - tau0 - 8]);
            uint4 p1 = *reinterpret_cast<const uint4*>(&sei[base - tau0 - 6]);
            uint4 p2 = *reinterpret_cast<const uint4*>(&sei[base - tau0 - 4]);
            uint4 p3 = *reinterpret_cast<const uint4*>(&sei[base - tau0 - 2]);
            rv[0] = ((unsigned long long)p0.y << 32) | p0.x;
            rv[1] = ((unsigned long long)p0.w << 32) | p0.z;
            rv[2] = ((unsigned long long)p1.y << 32) | p1.x;
            rv[3] = ((unsigned long long)p1.w << 32) | p1.z;
            rv[4] = ((unsigned long long)p2.y << 32) | p2.x;
            rv[5] = ((unsigned long long)p2.w << 32) | p2.z;
            rv[6] = ((unsigned long long)p3.y << 32) | p3.x;
            rv[7] = ((unsigned long long)p3.w << 32) | p3.z;
        }
        #pragma unroll
        for (int j = 0; j < 8; j++) {
            unsigned long long wv =
                *reinterpret_cast<const unsigned long long*>(&wei[tau0 + j]);
            #pragma unroll
            for (int i = 0; i < 8; i++)
                asm("fma.rn.f32x2 %0, %1, %2, %3;"
                    : "=l"(acc2[i]) : "l"(ev[i]), "l"(wv), "l"(acc2[i]));
            #pragma unroll
            for (int i = 7; i > 0; i--) ev[i] = ev[i - 1];
            ev[0] = rv[7 - j];                  // = sei[base - (tau0+j) - 1]
        }
    }
    float th = Theta[s];
    #pragma unroll
    for (int i = 0; i < 8; i++) {
        float lo = __uint_as_float((unsigned)(acc2[i] & 0xffffffffull));
        float hi = __uint_as_float((unsigned)(acc2[i] >> 32));
        int t = t0 + threadIdx.x * 8 + i;
        if (t < TLEN) g_A[s * RT + t] = lo + hi + th;
    }
}

// ---------------------------------------------------------------------------
// "Recurrence": C_den strictly upper triangular ->
//   out_i[t] = tanh(A_i[t] + sum_{j>i} Wd[i][j] * out_j[t-1])
// is a 20-level feed-forward DAG. 256-t blocks with a 19-t recomputed halo;
// no cross-block dependency. final[t] = out_0[t]*exp(W_sub[0]) + V_o.
#define R_BT 256
#define R_H  19

__global__ void __launch_bounds__(256) k_recur(const float* __restrict__ W_sub,
                                               const float* __restrict__ V_o,
                                               float* __restrict__ outF)
{
    __shared__ float so[R_BT + R_H][21];   // pitch 21 -> conflict free
    __shared__ float wd[SUBN][SUBN];
    const int t0 = blockIdx.x * R_BT;

    for (int r = threadIdx.x; r < (R_BT + R_H) * 21; r += 256)
        (&so[0][0])[r] = 0.f;               // zero == initial state for t<0
    for (int r = threadIdx.x; r < SUBN * SUBN; r += 256)
        (&wd[0][0])[r] = g_Wd[r];
    __syncthreads();

    for (int i = SUBN - 1; i >= 0; i--) {
        for (int l = threadIdx.x; l < R_BT + R_H; l += 256) {
            int t = t0 - R_H + l;
            if (l >= R_H - i && t >= 0 && t < TLEN) {
                float x = g_A[i * RT + t];
                float sum = 0.f;
                for (int jj = i + 1; jj < SUBN; jj++)
                    sum = fmaf(wd[i][jj], so[l - 1][jj], sum);
                so[l][i] = tanhf(x + sum);
            }
        }
        __syncthreads();
    }

    float g0 = expf(W_sub[0]);
    float vo = V_o[0];
    for (int l = R_H + threadIdx.x; l < R_BT + R_H; l += 256) {
        int t = t0 - R_H + l;
        if (t < TLEN) outF[t] = so[l][0] * g0 + vo;
    }
}

// ---------------------------------------------------------------------------
extern "C" void kernel_launch(void* const* d_in, const int* in_sizes, int n_in,
                              void* d_out, int out_size)
{
    if (n_in < 14) return;
    const float* S_e   = (const float*)d_in[0];
    const float* S_i   = (const float*)d_in[1];
    const float* temp  = (const float*)d_in[2];
    const int*   test  = (const int*)  d_in[3];
    const float* u_e   = (const float*)d_in[4];
    const float* u_i   = (const float*)d_in[5];
    const float* u_den = (const float*)d_in[6];
    const float* W_syn = (const float*)d_in[7];
    const float* W_sub = (const float*)d_in[8];
    const float* V_o   = (const float*)d_in[9];
    const float* Theta = (const float*)d_in[10];
    const float* Ce_l  = (const float*)d_in[11];
    const float* Ci_l  = (const float*)d_in[12];
    const float* Cd_r  = (const float*)d_in[13];

    // outputs concatenated in reference return order:
    // final[50000], out_filters[40*200], C_den[400], C_syn_e[40000], C_syn_i[10000]
    float* out = (float*)d_out;
    const int OF_FILT = TLEN;
    const int OF_CDEN = TLEN + 2 * SUBN * TNO;
    const int OF_CE   = OF_CDEN + SUBN * SUBN;
    const int OF_CI   = OF_CE + SUBN * ENO;
    const int OF_END  = OF_CI + SUBN * INO;
    float* o_final = out;
    float* o_filt = (out_size >= OF_CDEN) ? out + OF_FILT : nullptr;
    float* o_cden = (out_size >= OF_CE)   ? out + OF_CDEN : nullptr;
    float* o_ce   = (out_size >= OF_CI)   ? out + OF_CE   : nullptr;
    float* o_ci   = (out_size >= OF_END)  ? out + OF_CI   : nullptr;

    // 1) assignment matrices (must precede GEMM)
    k_csyn<<<(ENO + 127) / 128, 128>>>(Ce_l, u_e, temp, test, o_ce, ENO, 0);
    k_csyn<<<(INO + 127) / 128, 128>>>(Ci_l, u_i, temp, test, o_ci, INO, 1);
    k_cden<<<1, 32>>>(Cd_r, u_den, W_sub, temp, test, o_cden);
    if (o_filt)
        k_filtout<<<(2 * SUBN * TNO + 255) / 256, 256>>>(W_syn, o_filt);

    // 2) routing GEMMs (dominant cost): y=0 -> e (K=2000), y=1 -> i (K=500)
    {
        dim3 grid((TLEN + G_BT - 1) / G_BT, 2);
        k_gemm<<<grid, G_TH>>>(S_e, S_i);
    }

    // 3) causal FIR + Theta (packed e/i f32x2)
    {
        dim3 grid((TLEN + F_BT - 1) / F_BT, SUBN);
        k_filter2<<<grid, F_TH>>>(W_syn, Theta);
    }

    // 4) triangular DAG "recurrence" + final output
    k_recur<<<(TLEN + R_BT - 1) / R_BT, 256>>>(W_sub, V_o, o_final);
}

// round 6
// speedup vs baseline: 1.0999x; 1.0999x over previous
#include <cuda_runtime.h>
#include <cstdint>

// ---------------------------------------------------------------------------
// Tree_Stoch_GLM: gumbel-softmax routing + skinny GEMM + causal FIR +
// triangular "recurrence" (a 20-level feed-forward DAG in time, NOT a scan).
#define SUBN 20
#define TLEN 50000
#define TNO  200
#define ENO  2000
#define INO  500
#define RT   50048        // padded row stride for [20][T] buffers
#define EPSG 1e-7f

// ------------------------- scratch (device globals) ------------------------
__device__ float g_Ce[SUBN * ENO];
__device__ float g_Ci[SUBN * INO];
__device__ float g_Wd[SUBN * SUBN];     // C_den[i][j] * exp(W_sub[j])
__device__ float g_synTe[SUBN * RT];    // syn_e transposed [s][t]
__device__ float g_synTi[SUBN * RT];
__device__ float g_A[SUBN * RT];        // filtered_e+filtered_i+Theta, [s][t]

// ---------------------------------------------------------------------------
// Setup helpers (device functions used by the single merged setup kernel)

__device__ __forceinline__ void do_csyn(const float* __restrict__ logit,
                                        const float* __restrict__ u,
                                        float tp, int test,
                                        float* __restrict__ Cs,
                                        float* __restrict__ Cout, int E, int j)
{
    if (j >= E) return;
    float v[SUBN];
    if (test) {
        int am = 0; float b = logit[j];
        #pragma unroll
        for (int s = 1; s < SUBN; s++) {
            float l = logit[s * E + j];
            if (l > b) { b = l; am = s; }
        }
        #pragma unroll
        for (int s = 0; s < SUBN; s++) v[s] = (s == am) ? 1.f : 0.f;
    } else {
        float mx = -3.0e38f;
        #pragma unroll
        for (int s = 0; s < SUBN; s++) {
            float uu = u[s * E + j];
            float g = -logf(-logf(uu + EPSG) + EPSG);
            float y = (logit[s * E + j] + g) / tp;
            v[s] = y;
            mx = fmaxf(mx, y);
        }
        float sum = 0.f;
        #pragma unroll
        for (int s = 0; s < SUBN; s++) { v[s] = expf(v[s] - mx); sum += v[s]; }
        float inv = 1.f / sum;
        #pragma unroll
        for (int s = 0; s < SUBN; s++) v[s] *= inv;
    }
    #pragma unroll
    for (int s = 0; s < SUBN; s++) {
        Cs[s * E + j] = v[s];
        if (Cout) Cout[s * E + j] = v[s];
    }
}

// C_den column j: candidates rows 0..j-1 at linear offset j*(j-1)/2 - 1.
// Gumbel noise divided by temp (raw logits NOT), matching the reference.
__device__ __forceinline__ void do_cden(const float* __restrict__ raw,
                                        const float* __restrict__ u_den,
                                        const float* __restrict__ W_sub,
                                        float tp, int test,
                                        float* __restrict__ Cout, int j)
{
    float col[SUBN];
    #pragma unroll
    for (int r = 0; r < SUBN; r++) col[r] = 0.f;

    if (j == 1) col[0] = 1.f;
    if (j >= 2) {
        int off = j * (j - 1) / 2 - 1;
        if (test) {
            int am = 0; float b = raw[off];
            for (int r = 1; r < j; r++)
                if (raw[off + r] > b) { b = raw[off + r]; am = r; }
            col[am] = 1.f;
        } else {
            float v[SUBN];
            float mx = -3.0e38f;
            for (int r = 0; r < j; r++) {
                float uu = u_den[off + r];
                float g = -logf(-logf(uu + EPSG) + EPSG);
                v[r] = raw[off + r] + g / tp;
                mx = fmaxf(mx, v[r]);
            }
            float sum = 0.f;
            for (int r = 0; r < j; r++) { v[r] = expf(v[r] - mx); sum += v[r]; }
            float inv = 1.f / sum;
            for (int r = 0; r < j; r++) col[r] = v[r] * inv;
        }
    }
    float gj = expf(W_sub[j]);
    #pragma unroll
    for (int r = 0; r < SUBN; r++) {
        if (Cout) Cout[r * SUBN + j] = col[r];
        g_Wd[r * SUBN + j] = col[r] * gj;
    }
}

// One merged setup kernel: blocks [0,16) csyn_e, [16,20) csyn_i, 20 cden,
// [21,84) out_filters permute.  128 threads per block.
__global__ void __launch_bounds__(128) k_setup(
    const float* __restrict__ Ce_l, const float* __restrict__ u_e,
    const float* __restrict__ Ci_l, const float* __restrict__ u_i,
    const float* __restrict__ Cd_r, const float* __restrict__ u_den,
    const float* __restrict__ W_syn, const float* __restrict__ W_sub,
    const float* __restrict__ temp, const int* __restrict__ test,
    float* __restrict__ o_ce, float* __restrict__ o_ci,
    float* __restrict__ o_cden, float* __restrict__ o_filt)
{
    const int b = blockIdx.x;
    const float tp = *temp;
    const int ts = *test;
    if (b < 16) {
        do_csyn(Ce_l, u_e, tp, ts, g_Ce, o_ce, ENO, b * 128 + threadIdx.x);
    } else if (b < 20) {
        do_csyn(Ci_l, u_i, tp, ts, g_Ci, o_ci, INO, (b - 16) * 128 + threadIdx.x);
    } else if (b == 20) {
        if (threadIdx.x < SUBN)
            do_cden(Cd_r, u_den, W_sub, tp, ts, o_cden, threadIdx.x);
    } else {
        if (!o_filt) return;
        int idx = (b - 21) * 128 + threadIdx.x;
        if (idx < 2 * SUBN * TNO) {
            int r = idx / TNO, c = idx % TNO;
            int ch = r / SUBN, s = r % SUBN;
            o_filt[idx] = W_syn[s * (TNO * 2) + c * 2 + ch];
        }
    }
}

// ---------------------------------------------------------------------------
// Skinny GEMM v2: synT[s][t] = sum_k S[t][k] * C[s][k]  (N=20).
// gridDim.y: 0 -> e (K=2000), 1 -> i (K=500).
// 128 threads; warp w owns subunits 5w..5w+4; lane L owns t-pairs
// {2L + 64p, p=0..3} within a 256-t tile. Inner loop per kk:
//   4 conflict-free LDS.64 (S pairs) + 5 broadcast LDS.64 (pre-splatted C)
//   + 20 FFMA2  -> pipe-bound on the FMA pipe.
// Software pipelining: next K-chunk prefetched into registers during compute.
#define G_BT 256
#define G_KC 20
#define G_TH 128
#define G_PITCH 258

__global__ void __launch_bounds__(G_TH) k_gemm(const float* __restrict__ Se,
                                               const float* __restrict__ Si)
{
    __shared__ __align__(16) float  sS[G_KC][G_PITCH];   // [k][t]
    __shared__ __align__(8)  float2 sC2[SUBN][G_KC];     // splatted {c,c}

    const int which = blockIdx.y;
    const float* __restrict__ S  = which ? Si : Se;
    const float* __restrict__ Cs = which ? g_Ci : g_Ce;
    float* __restrict__ synT     = which ? g_synTi : g_synTe;
    const int K = which ? INO : ENO;

    const int t0   = blockIdx.x * G_BT;
    const int w    = threadIdx.x >> 5;
    const int lane = threadIdx.x & 31;

    // per-thread staging coords (10 float4 per chunk)
    int srow[10], scol[10];
    const float* sptr[10];
    #pragma unroll
    for (int it = 0; it < 10; it++) {
        int lin = threadIdx.x + it * G_TH;   // 0..1279
        int row = lin / 5;                   // t within tile (0..255)
        int c4  = lin % 5;
        srow[it] = row; scol[it] = c4 * 4;
        int t = t0 + row; if (t > TLEN - 1) t = TLEN - 1;
        sptr[it] = &S[(size_t)t * K + c4 * 4];
    }

    unsigned long long acc[4][5];
    #pragma unroll
    for (int p = 0; p < 4; p++)
        #pragma unroll
        for (int s = 0; s < 5; s++) acc[p][s] = 0ull;

    float4 pf[10];
    #pragma unroll
    for (int it = 0; it < 10; it++)
        pf[it] = *reinterpret_cast<const float4*>(sptr[it]);

    for (int k0 = 0; k0 < K; k0 += G_KC) {
        __syncthreads();    // previous compute done; smem safe to overwrite
        #pragma unroll
        for (int it = 0; it < 10; it++) {
            sS[scol[it] + 0][srow[it]] = pf[it].x;
            sS[scol[it] + 1][srow[it]] = pf[it].y;
            sS[scol[it] + 2][srow[it]] = pf[it].z;
            sS[scol[it] + 3][srow[it]] = pf[it].w;
        }
        // splat C chunk: 400 entries, each warp-broadcastable later
        for (int lin = threadIdx.x; lin < SUBN * G_KC; lin += G_TH) {
            int s = lin / G_KC, kk = lin % G_KC;
            float c = Cs[s * K + k0 + kk];
            sC2[s][kk] = make_float2(c, c);
        }
        __syncthreads();

        if (k0 + G_KC < K) {
            #pragma unroll
            for (int it = 0; it < 10; it++)
                pf[it] = *reinterpret_cast<const float4*>(sptr[it] + k0 + G_KC);
        }

        #pragma unroll
        for (int kk = 0; kk < G_KC; kk++) {
            unsigned long long a[4];
            #pragma unroll
            for (int p = 0; p < 4; p++)
                a[p] = *reinterpret_cast<const unsigned long long*>(
                           &sS[kk][p * 64 + 2 * lane]);
            #pragma unroll
            for (int s = 0; s < 5; s++) {
                unsigned long long c2 =
                    *reinterpret_cast<const unsigned long long*>(&sC2[w * 5 + s][kk]);
                #pragma unroll
                for (int p = 0; p < 4; p++)
                    asm("fma.rn.f32x2 %0, %1, %2, %3;"
                        : "=l"(acc[p][s]) : "l"(a[p]), "l"(c2), "l"(acc[p][s]));
            }
        }
    }

    #pragma unroll
    for (int s = 0; s < 5; s++)
        #pragma unroll
        for (int p = 0; p < 4; p++) {
            int t = t0 + p * 64 + 2 * lane;     // even; TLEN even
            if (t < TLEN)
                *reinterpret_cast<unsigned long long*>(
                    &synT[(w * 5 + s) * RT + t]) = acc[p][s];
        }
}

// ---------------------------------------------------------------------------
// Causal FIR (200 taps), e+i streams packed as f32x2, fused + Theta:
//   A[s][t] = Theta[s] + sum_tau (synTe[t-tau]*We[tau] + synTi[t-tau]*Wi[tau])
// Rolling packed register window; refills batched 8 taps via 4 x LDS.128.
#define F_BT 2048
#define F_TH 256
#define F_PAD 9                                // front pad -> base even
#define F_W  (F_BT + TNO - 1 + F_PAD)          // 2256 float2 slots

__global__ void __launch_bounds__(F_TH) k_filter(const float* __restrict__ W_syn,
                                                 const float* __restrict__ Theta)
{
    __shared__ __align__(16) float2 sei[F_W];
    __shared__ float2 wei[TNO];
    const int s  = blockIdx.y;
    const int t0 = blockIdx.x * F_BT;

    for (int l = threadIdx.x; l < F_W; l += F_TH) {
        int t = t0 - (TNO - 1) + (l - F_PAD);
        float2 v = make_float2(0.f, 0.f);
        if (l >= F_PAD && t >= 0 && t < TLEN) {
            v.x = g_synTe[s * RT + t];
            v.y = g_synTi[s * RT + t];
        }
        sei[l] = v;
    }
    if (threadIdx.x < TNO)   // W_syn[s][tau][{0,1}] is already {e,i} interleaved
        wei[threadIdx.x] = reinterpret_cast<const float2*>(W_syn + s * TNO * 2)[threadIdx.x];
    __syncthreads();

    const int base = F_PAD + (TNO - 1) + threadIdx.x * 8;   // even -> 16B aligned
    unsigned long long acc2[8], ev[8];
    #pragma unroll
    for (int i = 0; i < 8; i++) {
        acc2[i] = 0ull;
        ev[i] = *reinterpret_cast<const unsigned long long*>(&sei[base + i]);
    }

    for (int tau0 = 0; tau0 < TNO; tau0 += 8) {
        unsigned long long rv[8];   // rv[k] = sei[base - tau0 - 8 + k]
        {
            uint4 p0 = *reinterpret_cast<const uint4*>(&sei[base - tau0 - 8]);
            uint4 p1 = *reinterpret_cast<const uint4*>(&sei[base - tau0 - 6]);
            uint4 p2 = *reinterpret_cast<const uint4*>(&sei[base - tau0 - 4]);
            uint4 p3 = *reinterpret_cast<const uint4*>(&sei[base - tau0 - 2]);
            rv[0] = ((unsigned long long)p0.y << 32) | p0.x;
            rv[1] = ((unsigned long long)p0.w << 32) | p0.z;
            rv[2] = ((unsigned long long)p1.y << 32) | p1.x;
            rv[3] = ((unsigned long long)p1.w << 32) | p1.z;
            rv[4] = ((unsigned long long)p2.y << 32) | p2.x;
            rv[5] = ((unsigned long long)p2.w << 32) | p2.z;
            rv[6] = ((unsigned long long)p3.y << 32) | p3.x;
            rv[7] = ((unsigned long long)p3.w << 32) | p3.z;
        }
        #pragma unroll
        for (int j = 0; j < 8; j++) {
            unsigned long long wv =
                *reinterpret_cast<const unsigned long long*>(&wei[tau0 + j]);
            #pragma unroll
            for (int i = 0; i < 8; i++)
                asm("fma.rn.f32x2 %0, %1, %2, %3;"
                    : "=l"(acc2[i]) : "l"(ev[i]), "l"(wv), "l"(acc2[i]));
            #pragma unroll
            for (int i = 7; i > 0; i--) ev[i] = ev[i - 1];
            ev[0] = rv[7 - j];                  // = sei[base - (tau0+j) - 1]
        }
    }
    float th = Theta[s];
    #pragma unroll
    for (int i = 0; i < 8; i++) {
        float lo = __uint_as_float((unsigned)(acc2[i] & 0xffffffffull));
        float hi = __uint_as_float((unsigned)(acc2[i] >> 32));
        int t = t0 + threadIdx.x * 8 + i;
        if (t < TLEN) g_A[s * RT + t] = lo + hi + th;
    }
}

// ---------------------------------------------------------------------------
// "Recurrence": C_den strictly upper triangular ->
//   out_i[t] = tanh(A_i[t] + sum_{j>i} Wd[i][j] * out_j[t-1])
// is a 20-level feed-forward DAG. 256-t blocks with a 19-t recomputed halo;
// no cross-block dependency. final[t] = out_0[t]*exp(W_sub[0]) + V_o.
#define R_BT 256
#define R_H  19

__global__ void __launch_bounds__(256) k_recur(const float* __restrict__ W_sub,
                                               const float* __restrict__ V_o,
                                               float* __restrict__ outF)
{
    __shared__ float so[R_BT + R_H][21];   // pitch 21 -> conflict free
    __shared__ float wd[SUBN][SUBN];
    const int t0 = blockIdx.x * R_BT;

    for (int r = threadIdx.x; r < (R_BT + R_H) * 21; r += 256)
        (&so[0][0])[r] = 0.f;               // zero == initial state for t<0
    for (int r = threadIdx.x; r < SUBN * SUBN; r += 256)
        (&wd[0][0])[r] = g_Wd[r];
    __syncthreads();

    for (int i = SUBN - 1; i >= 0; i--) {
        for (int l = threadIdx.x; l < R_BT + R_H; l += 256) {
            int t = t0 - R_H + l;
            if (l >= R_H - i && t >= 0 && t < TLEN) {
                float x = g_A[i * RT + t];
                float sum = 0.f;
                for (int jj = i + 1; jj < SUBN; jj++)
                    sum = fmaf(wd[i][jj], so[l - 1][jj], sum);
                so[l][i] = tanhf(x + sum);
            }
        }
        __syncthreads();
    }

    float g0 = expf(W_sub[0]);
    float vo = V_o[0];
    for (int l = R_H + threadIdx.x; l < R_BT + R_H; l += 256) {
        int t = t0 - R_H + l;
        if (t < TLEN) outF[t] = so[l][0] * g0 + vo;
    }
}

// ---------------------------------------------------------------------------
extern "C" void kernel_launch(void* const* d_in, const int* in_sizes, int n_in,
                              void* d_out, int out_size)
{
    if (n_in < 14) return;
    const float* S_e   = (const float*)d_in[0];
    const float* S_i   = (const float*)d_in[1];
    const float* temp  = (const float*)d_in[2];
    const int*   test  = (const int*)  d_in[3];
    const float* u_e   = (const float*)d_in[4];
    const float* u_i   = (const float*)d_in[5];
    const float* u_den = (const float*)d_in[6];
    const float* W_syn = (const float*)d_in[7];
    const float* W_sub = (const float*)d_in[8];
    const float* V_o   = (const float*)d_in[9];
    const float* Theta = (const float*)d_in[10];
    const float* Ce_l  = (const float*)d_in[11];
    const float* Ci_l  = (const float*)d_in[12];
    const float* Cd_r  = (const float*)d_in[13];

    // outputs concatenated in reference return order:
    // final[50000], out_filters[40*200], C_den[400], C_syn_e[40000], C_syn_i[10000]
    float* out = (float*)d_out;
    const int OF_FILT = TLEN;
    const int OF_CDEN = TLEN + 2 * SUBN * TNO;
    const int OF_CE   = OF_CDEN + SUBN * SUBN;
    const int OF_CI   = OF_CE + SUBN * ENO;
    const int OF_END  = OF_CI + SUBN * INO;
    float* o_final = out;
    float* o_filt = (out_size >= OF_CDEN) ? out + OF_FILT : nullptr;
    float* o_cden = (out_size >= OF_CE)   ? out + OF_CDEN : nullptr;
    float* o_ce   = (out_size >= OF_CI)   ? out + OF_CE   : nullptr;
    float* o_ci   = (out_size >= OF_END)  ? out + OF_CI   : nullptr;

    // 1) one merged setup launch: csyn_e, csyn_i, cden, filter permute
    k_setup<<<84, 128>>>(Ce_l, u_e, Ci_l, u_i, Cd_r, u_den, W_syn, W_sub,
                         temp, test, o_ce, o_ci, o_cden, o_filt);

    // 2) routing GEMMs (dominant cost): y=0 -> e (K=2000), y=1 -> i (K=500)
    {
        dim3 grid((TLEN + G_BT - 1) / G_BT, 2);
        k_gemm<<<grid, G_TH>>>(S_e, S_i);
    }

    // 3) causal FIR + Theta (packed e/i f32x2)
    {
        dim3 grid((TLEN + F_BT - 1) / F_BT, SUBN);
        k_filter<<<grid, F_TH>>>(W_syn, Theta);
    }

    // 4) triangular DAG "recurrence" + final output
    k_recur<<<(TLEN + R_BT - 1) / R_BT, 256>>>(W_sub, V_o, o_final);
}

// round 8
// speedup vs baseline: 1.5316x; 1.3925x over previous
#include <cuda_runtime.h>
#include <cstdint>

// ---------------------------------------------------------------------------
// Tree_Stoch_GLM: gumbel-softmax routing + skinny GEMM + causal FIR +
// triangular "recurrence" (a 20-level feed-forward DAG in time, NOT a scan).
#define SUBN 20
#define TLEN 50000
#define TNO  200
#define ENO  2000
#define INO  500
#define RT   50048        // padded row stride for [20][T] buffers
#define EPSG 1e-7f

// ------------------------- scratch (device globals) ------------------------
__device__ float g_Ce[SUBN * ENO];
__device__ float g_Ci[SUBN * INO];
__device__ float g_Wd[SUBN * SUBN];       // C_den[i][j] * exp(W_sub[j])
__device__ float g_pe[4][SUBN * RT];      // e-GEMM K-split partials [s][t]
__device__ float g_synTi[SUBN * RT];      // i-GEMM result [s][t]
__device__ float g_A[SUBN * RT];          // filtered_e+filtered_i+Theta, [s][t]

// ---------------------------------------------------------------------------
// Setup helpers (device functions used by the single merged setup kernel)

__device__ __forceinline__ void do_csyn(const float* __restrict__ logit,
                                        const float* __restrict__ u,
                                        float tp, int test,
                                        float* __restrict__ Cs,
                                        float* __restrict__ Cout, int E, int j)
{
    if (j >= E) return;
    float v[SUBN];
    if (test) {
        int am = 0; float b = logit[j];
        #pragma unroll
        for (int s = 1; s < SUBN; s++) {
            float l = logit[s * E + j];
            if (l > b) { b = l; am = s; }
        }
        #pragma unroll
        for (int s = 0; s < SUBN; s++) v[s] = (s == am) ? 1.f : 0.f;
    } else {
        float mx = -3.0e38f;
        #pragma unroll
        for (int s = 0; s < SUBN; s++) {
            float uu = u[s * E + j];
            float g = -logf(-logf(uu + EPSG) + EPSG);
            float y = (logit[s * E + j] + g) / tp;
            v[s] = y;
            mx = fmaxf(mx, y);
        }
        float sum = 0.f;
        #pragma unroll
        for (int s = 0; s < SUBN; s++) { v[s] = expf(v[s] - mx); sum += v[s]; }
        float inv = 1.f / sum;
        #pragma unroll
        for (int s = 0; s < SUBN; s++) v[s] *= inv;
    }
    #pragma unroll
    for (int s = 0; s < SUBN; s++) {
        Cs[s * E + j] = v[s];
        if (Cout) Cout[s * E + j] = v[s];
    }
}

// C_den column j: candidates rows 0..j-1 at linear offset j*(j-1)/2 - 1.
// Gumbel noise divided by temp (raw logits NOT), matching the reference.
__device__ __forceinline__ void do_cden(const float* __restrict__ raw,
                                        const float* __restrict__ u_den,
                                        const float* __restrict__ W_sub,
                                        float tp, int test,
                                        float* __restrict__ Cout, int j)
{
    float col[SUBN];
    #pragma unroll
    for (int r = 0; r < SUBN; r++) col[r] = 0.f;

    if (j == 1) col[0] = 1.f;
    if (j >= 2) {
        int off = j * (j - 1) / 2 - 1;
        if (test) {
            int am = 0; float b = raw[off];
            for (int r = 1; r < j; r++)
                if (raw[off + r] > b) { b = raw[off + r]; am = r; }
            col[am] = 1.f;
        } else {
            float v[SUBN];
            float mx = -3.0e38f;
            for (int r = 0; r < j; r++) {
                float uu = u_den[off + r];
                float g = -logf(-logf(uu + EPSG) + EPSG);
                v[r] = raw[off + r] + g / tp;
                mx = fmaxf(mx, v[r]);
            }
            float sum = 0.f;
            for (int r = 0; r < j; r++) { v[r] = expf(v[r] - mx); sum += v[r]; }
            float inv = 1.f / sum;
            for (int r = 0; r < j; r++) col[r] = v[r] * inv;
        }
    }
    float gj = expf(W_sub[j]);
    #pragma unroll
    for (int r = 0; r < SUBN; r++) {
        if (Cout) Cout[r * SUBN + j] = col[r];
        g_Wd[r * SUBN + j] = col[r] * gj;
    }
}

// One merged setup kernel: blocks [0,16) csyn_e, [16,20) csyn_i, 20 cden,
// [21,84) out_filters permute.  128 threads per block.
__global__ void __launch_bounds__(128) k_setup(
    const float* __restrict__ Ce_l, const float* __restrict__ u_e,
    const float* __restrict__ Ci_l, const float* __restrict__ u_i,
    const float* __restrict__ Cd_r, const float* __restrict__ u_den,
    const float* __restrict__ W_syn, const float* __restrict__ W_sub,
    const float* __restrict__ temp, const int* __restrict__ test,
    float* __restrict__ o_ce, float* __restrict__ o_ci,
    float* __restrict__ o_cden, float* __restrict__ o_filt)
{
    const int b = blockIdx.x;
    const float tp = *temp;
    const int ts = *test;
    if (b < 16) {
        do_csyn(Ce_l, u_e, tp, ts, g_Ce, o_ce, ENO, b * 128 + threadIdx.x);
    } else if (b < 20) {
        do_csyn(Ci_l, u_i, tp, ts, g_Ci, o_ci, INO, (b - 16) * 128 + threadIdx.x);
    } else if (b == 20) {
        if (threadIdx.x < SUBN)
            do_cden(Cd_r, u_den, W_sub, tp, ts, o_cden, threadIdx.x);
    } else {
        if (!o_filt) return;
        int idx = (b - 21) * 128 + threadIdx.x;
        if (idx < 2 * SUBN * TNO) {
            int r = idx / TNO, c = idx % TNO;
            int ch = r / SUBN, s = r % SUBN;
            o_filt[idx] = W_syn[s * (TNO * 2) + c * 2 + ch];
        }
    }
}

// ---------------------------------------------------------------------------
// Skinny GEMM v3: K-split for occupancy.
// blockIdx.y in [0,5): y<4 -> e stream, K-range [500y, 500y+500) -> g_pe[y]
//                      y==4 -> i stream, K=500 -> g_synTi
// 256 threads = 8 warps; warp w: s-group (w&3)*5, t-half (w>>2).
// Lane L owns t-pairs {(2h+p)*64 + 2L, p=0..1} in a 256-t tile.
// Inner loop per kk: 2 conflict-free LDS.64 + 5 broadcast LDS.64 + 10 FFMA2.
// Next K-chunk prefetched into registers during compute.
#define G_BT 256
#define G_KC 20
#define G_KS 500
#define G_TH 256
#define G_PITCH 258

__global__ void __launch_bounds__(G_TH) k_gemm(const float* __restrict__ Se,
                                               const float* __restrict__ Si)
{
    __shared__ __align__(16) float  sS[G_KC][G_PITCH];   // [k][t]
    __shared__ __align__(8)  float2 sC2[SUBN][G_KC];     // splatted {c,c}

    const int y = blockIdx.y;
    const int which = (y == 4);
    const float* __restrict__ S  = which ? Si : Se;
    const float* __restrict__ Cs = which ? g_Ci : g_Ce;
    float* __restrict__ synT     = which ? g_synTi : &g_pe[y][0];
    const int K     = which ? INO : ENO;
    const int kbase = which ? 0 : y * G_KS;

    const int t0   = blockIdx.x * G_BT;
    const int w    = threadIdx.x >> 5;
    const int lane = threadIdx.x & 31;
    const int sb   = (w & 3) * 5;      // subunit group
    const int th   = (w >> 2);         // t-half (0/1)

    // staging: 640 float4 per chunk across 256 threads -> 3 slots, guarded
    int srow[3], scol[3]; bool sok[3];
    const float* sptr[3];
    #pragma unroll
    for (int it = 0; it < 3; it++) {
        int lin = threadIdx.x + it * G_TH;   // 0..767
        sok[it] = (lin < 640);
        int row = lin / 5;                   // t within tile
        int c4  = lin % 5;
        srow[it] = row; scol[it] = c4 * 4;
        int t = t0 + row; if (t > TLEN - 1) t = TLEN - 1;
        sptr[it] = &S[(size_t)t * K + kbase + c4 * 4];
    }

    unsigned long long acc[2][5];
    #pragma unroll
    for (int p = 0; p < 2; p++)
        #pragma unroll
        for (int s = 0; s < 5; s++) acc[p][s] = 0ull;

    float4 pf[3];
    #pragma unroll
    for (int it = 0; it < 3; it++)
        if (sok[it]) pf[it] = *reinterpret_cast<const float4*>(sptr[it]);

    for (int k0 = 0; k0 < G_KS; k0 += G_KC) {
        __syncthreads();    // previous compute done; smem safe to overwrite
        #pragma unroll
        for (int it = 0; it < 3; it++)
            if (sok[it]) {
                sS[scol[it] + 0][srow[it]] = pf[it].x;
                sS[scol[it] + 1][srow[it]] = pf[it].y;
                sS[scol[it] + 2][srow[it]] = pf[it].z;
                sS[scol[it] + 3][srow[it]] = pf[it].w;
            }
        // splat C chunk: 400 entries
        for (int lin = threadIdx.x; lin < SUBN * G_KC; lin += G_TH) {
            int s = lin / G_KC, kk = lin % G_KC;
            float c = Cs[s * K + kbase + k0 + kk];
            sC2[s][kk] = make_float2(c, c);
        }
        __syncthreads();

        if (k0 + G_KC < G_KS) {
            #pragma unroll
            for (int it = 0; it < 3; it++)
                if (sok[it])
                    pf[it] = *reinterpret_cast<const float4*>(sptr[it] + k0 + G_KC);
        }

        #pragma unroll
        for (int kk = 0; kk < G_KC; kk++) {
            unsigned long long a[2];
            #pragma unroll
            for (int p = 0; p < 2; p++)
                a[p] = *reinterpret_cast<const unsigned long long*>(
                           &sS[kk][(th * 2 + p) * 64 + 2 * lane]);
            #pragma unroll
            for (int s = 0; s < 5; s++) {
                unsigned long long c2 =
                    *reinterpret_cast<const unsigned long long*>(&sC2[sb + s][kk]);
                #pragma unroll
                for (int p = 0; p < 2; p++)
                    asm("fma.rn.f32x2 %0, %1, %2, %3;"
                        : "=l"(acc[p][s]) : "l"(a[p]), "l"(c2), "l"(acc[p][s]));
            }
        }
    }

    #pragma unroll
    for (int s = 0; s < 5; s++)
        #pragma unroll
        for (int p = 0; p < 2; p++) {
            int t = t0 + (th * 2 + p) * 64 + 2 * lane;   // even; TLEN even
            if (t < TLEN)
                *reinterpret_cast<unsigned long long*>(
                    &synT[(sb + s) * RT + t]) = acc[p][s];
        }
}

// ---------------------------------------------------------------------------
// Causal FIR (200 taps). Load phase sums the 4 e-partials (K-split reduce is
// free here) and packs e+i as f32x2. Then rolling packed register window:
//   A[s][t] = Theta[s] + sum_tau (synTe[t-tau]*We[tau] + synTi[t-tau]*Wi[tau])
#define F_BT 2048
#define F_TH 256
#define F_PAD 9                                // front pad -> base even
#define F_W  (F_BT + TNO - 1 + F_PAD)          // 2256 float2 slots

__global__ void __launch_bounds__(F_TH) k_filter(const float* __restrict__ W_syn,
                                                 const float* __restrict__ Theta)
{
    __shared__ __align__(16) float2 sei[F_W];
    __shared__ float2 wei[TNO];
    const int s  = blockIdx.y;
    const int t0 = blockIdx.x * F_BT;

    for (int l = threadIdx.x; l < F_W; l += F_TH) {
        int t = t0 - (TNO - 1) + (l - F_PAD);
        float2 v = make_float2(0.f, 0.f);
        if (l >= F_PAD && t >= 0 && t < TLEN) {
            int idx = s * RT + t;
            v.x = (g_pe[0][idx] + g_pe[1][idx]) + (g_pe[2][idx] + g_pe[3][idx]);
            v.y = g_synTi[idx];
        }
        sei[l] = v;
    }
    if (threadIdx.x < TNO)   // W_syn[s][tau][{0,1}] is already {e,i} interleaved
        wei[threadIdx.x] = reinterpret_cast<const float2*>(W_syn + s * TNO * 2)[threadIdx.x];
    __syncthreads();

    const int base = F_PAD + (TNO - 1) + threadIdx.x * 8;   // even -> 16B aligned
    unsigned long long acc2[8], ev[8];
    #pragma unroll
    for (int i = 0; i < 8; i++) {
        acc2[i] = 0ull;
        ev[i] = *reinterpret_cast<const unsigned long long*>(&sei[base + i]);
    }

    for (int tau0 = 0; tau0 < TNO; tau0 += 8) {
        unsigned long long rv[8];   // rv[k] = sei[base - tau0 - 8 + k]
        {
            uint4 p0 = *reinterpret_cast<const uint4*>(&sei[base - tau0 - 8]);
            uint4 p1 = *reinterpret_cast<const uint4*>(&sei[base - tau0 - 6]);
            uint4 p2 = *reinterpret_cast<const uint4*>(&sei[base - tau0 - 4]);
            uint4 p3 = *reinterpret_cast<const uint4*>(&sei[base - tau0 - 2]);
            rv[0] = ((unsigned long long)p0.y << 32) | p0.x;
            rv[1] = ((unsigned long long)p0.w << 32) | p0.z;
            rv[2] = ((unsigned long long)p1.y << 32) | p1.x;
            rv[3] = ((unsigned long long)p1.w << 32) | p1.z;
            rv[4] = ((unsigned long long)p2.y << 32) | p2.x;
            rv[5] = ((unsigned long long)p2.w << 32) | p2.z;
            rv[6] = ((unsigned long long)p3.y << 32) | p3.x;
            rv[7] = ((unsigned long long)p3.w << 32) | p3.z;
        }
        #pragma unroll
        for (int j = 0; j < 8; j++) {
            unsigned long long wv =
                *reinterpret_cast<const unsigned long long*>(&wei[tau0 + j]);
            #pragma unroll
            for (int i = 0; i < 8; i++)
                asm("fma.rn.f32x2 %0, %1, %2, %3;"
                    : "=l"(acc2[i]) : "l"(ev[i]), "l"(wv), "l"(acc2[i]));
            #pragma unroll
            for (int i = 7; i > 0; i--) ev[i] = ev[i - 1];
            ev[0] = rv[7 - j];                  // = sei[base - (tau0+j) - 1]
        }
    }
    float th = Theta[s];
    #pragma unroll
    for (int i = 0; i < 8; i++) {
        float lo = __uint_as_float((unsigned)(acc2[i] & 0xffffffffull));
        float hi = __uint_as_float((unsigned)(acc2[i] >> 32));
        int t = t0 + threadIdx.x * 8 + i;
        if (t < TLEN) g_A[s * RT + t] = lo + hi + th;
    }
}

// ---------------------------------------------------------------------------
// "Recurrence" v2: C_den strictly upper triangular ->
//   out_i[t] = tanh(A_i[t] + sum_{j>i} Wd[i][j] * out_j[t-1])
// is a 20-level feed-forward DAG. One thread per halo slot (288 threads,
// 275 active); ALL 20 A-values preloaded into registers (one batched LDG
// wait instead of 20 serialized per-level loads — this was 23 us of exposed
// DRAM latency). final[t] = out_0[t]*exp(W_sub[0]) + V_o.
#define R_BT 256
#define R_H  19
#define R_W  (R_BT + R_H)      // 275
#define R_TH 288

__global__ void __launch_bounds__(R_TH) k_recur(const float* __restrict__ W_sub,
                                                const float* __restrict__ V_o,
                                                float* __restrict__ outF)
{
    __shared__ float so[R_W][21];   // pitch 21 -> conflict free
    __shared__ float wd[SUBN][SUBN];
    const int t0 = blockIdx.x * R_BT;
    const int l  = threadIdx.x;
    const int t  = t0 - R_H + l;
    const bool act = (l < R_W) && (t >= 0) && (t < TLEN);

    // preload A[i][t] for all 20 levels (coalesced, batched)
    float av[SUBN];
    #pragma unroll
    for (int i = 0; i < SUBN; i++)
        av[i] = act ? g_A[i * RT + t] : 0.f;

    if (l < R_W) {
        #pragma unroll
        for (int j = 0; j < 21; j++) so[l][j] = 0.f;   // zero == state for t<0
    }
    for (int r = l; r < SUBN * SUBN; r += R_TH)
        (&wd[0][0])[r] = g_Wd[r];
    __syncthreads();

    #pragma unroll
    for (int i = SUBN - 1; i >= 0; i--) {
        if (act && l >= R_H - i) {
            float sum = av[i];
            #pragma unroll
            for (int jj = i + 1; jj < SUBN; jj++)
                sum = fmaf(wd[i][jj], so[l - 1][jj], sum);
            so[l][i] = tanhf(sum);
        }
        __syncthreads();
    }

    float g0 = expf(W_sub[0]);
    float vo = V_o[0];
    if (act && l >= R_H) outF[t] = so[l][0] * g0 + vo;
}

// ---------------------------------------------------------------------------
extern "C" void kernel_launch(void* const* d_in, const int* in_sizes, int n_in,
                              void* d_out, int out_size)
{
    if (n_in < 14) return;
    const float* S_e   = (const float*)d_in[0];
    const float* S_i   = (const float*)d_in[1];
    const float* temp  = (const float*)d_in[2];
    const int*   test  = (const int*)  d_in[3];
    const float* u_e   = (const float*)d_in[4];
    const float* u_i   = (const float*)d_in[5];
    const float* u_den = (const float*)d_in[6];
    const float* W_syn = (const float*)d_in[7];
    const float* W_sub = (const float*)d_in[8];
    const float* V_o   = (const float*)d_in[9];
    const float* Theta = (const float*)d_in[10];
    const float* Ce_l  = (const float*)d_in[11];
    const float* Ci_l  = (const float*)d_in[12];
    const float* Cd_r  = (const float*)d_in[13];

    // outputs concatenated in reference return order:
    // final[50000], out_filters[40*200], C_den[400], C_syn_e[40000], C_syn_i[10000]
    float* out = (float*)d_out;
    const int OF_FILT = TLEN;
    const int OF_CDEN = TLEN + 2 * SUBN * TNO;
    const int OF_CE   = OF_CDEN + SUBN * SUBN;
    const int OF_CI   = OF_CE + SUBN * ENO;
    const int OF_END  = OF_CI + SUBN * INO;
    float* o_final = out;
    float* o_filt = (out_size >= OF_CDEN) ? out + OF_FILT : nullptr;
    float* o_cden = (out_size >= OF_CE)   ? out + OF_CDEN : nullptr;
    float* o_ce   = (out_size >= OF_CI)   ? out + OF_CE   : nullptr;
    float* o_ci   = (out_size >= OF_END)  ? out + OF_CI   : nullptr;

    // 1) one merged setup launch: csyn_e, csyn_i, cden, filter permute
    k_setup<<<84, 128>>>(Ce_l, u_e, Ci_l, u_i, Cd_r, u_den, W_syn, W_sub,
                         temp, test, o_ce, o_ci, o_cden, o_filt);

    // 2) routing GEMMs, K-split: y<4 -> e partials, y=4 -> i
    {
        dim3 grid((TLEN + G_BT - 1) / G_BT, 5);
        k_gemm<<<grid, G_TH>>>(S_e, S_i);
    }

    // 3) causal FIR + Theta (sums e-partials during load; packed e/i f32x2)
    {
        dim3 grid((TLEN + F_BT - 1) / F_BT, SUBN);
        k_filter<<<grid, F_TH>>>(W_syn, Theta);
    }

    // 4) triangular DAG "recurrence" + final output
    k_recur<<<(TLEN + R_BT - 1) / R_BT, R_TH>>>(W_sub, V_o, o_final);
}